// round 16
// baseline (speedup 1.0000x reference)
#include <cuda_runtime.h>
#include <cuda_bf16.h>
#include <cuda_fp16.h>
#include <math.h>
#include <stdint.h>

// Problem constants
#define Bb 4
#define Ss 2048
#define Dd 768
#define Hh 12
#define Ff 3072
#define Ll 4
#define DHh 64
#define Mrows (Bb*Ss)   // 8192

// ---------------------------------------------------------------------------
// Scratch (device globals; allocation is forbidden)
// ---------------------------------------------------------------------------
__device__ float g_x[Bb*Ss*Dd];
__device__ float g_q[Bb*Ss*Dd];
__device__ float g_k[Bb*Ss*Dd];
__device__ float g_v[Bb*Ss*Dd];
__device__ float g_attn[Bb*Ss*Dd];
__device__ float g_mid[Bb*Ss*Ff];

// Preprocessed (transposed [N,K] K-major) fp16 weights
__device__ __half g_wqkv[Ll*3*Dd*Dd];
__device__ __half g_wo[Ll*Dd*Dd];
__device__ __half g_w1[Ll*Ff*Dd];
__device__ __half g_w2[Ll*Dd*Ff];

__device__ __forceinline__ float gelu_exact(float v) {
    return 0.5f * v * (1.0f + erff(v * 0.70710678118654752f));
}

// fp16 mma: D = A(f16) * B(f16) + D, fp32 accum
__device__ __forceinline__ void mma16816(float* c, const uint32_t* a,
                                         const uint32_t* b) {
    asm volatile(
        "mma.sync.aligned.m16n8k16.row.col.f32.f16.f16.f32 "
        "{%0,%1,%2,%3}, {%4,%5,%6,%7}, {%8,%9}, {%0,%1,%2,%3};"
        : "+f"(c[0]), "+f"(c[1]), "+f"(c[2]), "+f"(c[3])
        : "r"(a[0]), "r"(a[1]), "r"(a[2]), "r"(a[3]), "r"(b[0]), "r"(b[1]));
}

__device__ __forceinline__ void ldmx4(uint32_t* r, uint32_t addr) {
    asm volatile(
        "ldmatrix.sync.aligned.m8n8.x4.shared.b16 {%0,%1,%2,%3}, [%4];"
        : "=r"(r[0]), "=r"(r[1]), "=r"(r[2]), "=r"(r[3]) : "r"(addr));
}

__device__ __forceinline__ void ldmx4t(uint32_t* r, uint32_t addr) {
    asm volatile(
        "ldmatrix.sync.aligned.m8n8.x4.trans.shared.b16 {%0,%1,%2,%3}, [%4];"
        : "=r"(r[0]), "=r"(r[1]), "=r"(r[2]), "=r"(r[3]) : "r"(addr));
}

__device__ __forceinline__ uint32_t smem_u32(const void* p) {
    uint32_t a;
    asm("{ .reg .u64 tmp; cvta.to.shared.u64 tmp, %1; cvt.u32.u64 %0, tmp; }"
        : "=r"(a) : "l"(p));
    return a;
}

__device__ __forceinline__ uint32_t pack_h2(__half a, __half b) {
    __half2 p; p.x = a; p.y = b;
    return *(uint32_t*)&p;
}

__device__ __forceinline__ uint32_t cvt2h(float x, float y) {
    return pack_h2(__float2half_rn(x), __float2half_rn(y));
}

// ---------------------------------------------------------------------------
// Weight preprocessing (3 launches): transpose [K,N] -> [N,K], fp16.
// ---------------------------------------------------------------------------
__global__ void __launch_bounds__(256) transpose_dd_kernel(
    const float* __restrict__ Wq, const float* __restrict__ Wk,
    const float* __restrict__ Wv, const float* __restrict__ Wo,
    __half* __restrict__ qkv, __half* __restrict__ wo)
{
    __shared__ float tile[32][33];
    const int z = blockIdx.z;
    const int layer = z >> 2, which = z & 3;
    const size_t DD = (size_t)Dd * Dd;
    const float* src =
        (which == 0 ? Wq : which == 1 ? Wk : which == 2 ? Wv : Wo)
        + (size_t)layer * DD;
    __half* oh;
    int rowOff;
    if (which < 3) {
        oh = qkv + (size_t)layer * 3 * DD;
        rowOff = which * Dd;
    } else {
        oh = wo + (size_t)layer * DD;
        rowOff = 0;
    }
    const int nb = blockIdx.x * 32, kb = blockIdx.y * 32;
    const int tx = threadIdx.x & 31, ty = threadIdx.x >> 5;
    #pragma unroll
    for (int j = 0; j < 32; j += 8)
        tile[ty + j][tx] = src[(size_t)(kb + ty + j) * Dd + nb + tx];
    __syncthreads();
    #pragma unroll
    for (int j = 0; j < 32; j += 8) {
        float v = tile[tx][ty + j];
        int n = nb + ty + j, k = kb + tx;
        oh[(size_t)(rowOff + n) * Dd + k] = __float2half_rn(v);
    }
}

__global__ void __launch_bounds__(256) transpose_split_kernel(
    const float* __restrict__ W, __half* __restrict__ oh,
    int K, int N, size_t LS)
{
    __shared__ float tile[32][33];
    const float* Wl = W + (size_t)blockIdx.z * LS;
    __half* ohl = oh + (size_t)blockIdx.z * LS;
    const int nb = blockIdx.x * 32, kb = blockIdx.y * 32;
    const int tx = threadIdx.x & 31, ty = threadIdx.x >> 5;
    #pragma unroll
    for (int j = 0; j < 32; j += 8)
        tile[ty + j][tx] = Wl[(size_t)(kb + ty + j) * N + nb + tx];
    __syncthreads();
    #pragma unroll
    for (int j = 0; j < 32; j += 8) {
        float v = tile[tx][ty + j];
        int n = nb + ty + j, k = kb + tx;
        ohl[(size_t)n * K + k] = __float2half_rn(v);
    }
}

// ---------------------------------------------------------------------------
// Tensor-core GEMM (R15 + hoisted LDSM): CTA 128x128, 8 warps (32x64 warp
// tile), BK=32, double-buffered smem, register-prefetch LDG, one sync per
// chunk. ALL 12 ldmatrix of the chunk issue before any mma so their
// latencies overlap; the 32 mma then stream without per-group LDS stalls.
// PURE fp16: C = A(f16) * W(f16)^T, fp32 accum.
// mode: 0 = +bias, 1 = +bias +exact GELU, 2 = QKV split (768-col outputs).
// ---------------------------------------------------------------------------
#define BKP 40
#define TILE_E (128 * BKP)
#define STAGE_E (2 * TILE_E)          // A, W
#define GEMM_SMEM (2 * STAGE_E * 2)   // 40960 B

__global__ void __launch_bounds__(256, 1)
tc_gemm_kernel(const float* __restrict__ A,
               const __half* __restrict__ W,
               const float* __restrict__ bias,
               float* __restrict__ C0, float* __restrict__ C1,
               float* __restrict__ C2,
               int N, int K, int mode)
{
    extern __shared__ __half sm[];
    const uint32_t sbase = smem_u32(sm);
    const int t   = threadIdx.x;
    const int wid = t >> 5, l = t & 31;
    const int wm  = wid & 3;
    const int wn  = wid >> 2;
    const int n0  = blockIdx.x * 128;
    const int m0  = blockIdx.y * 128;

    const float* Ab = A + (size_t)m0 * K;
    const __half* Wb = W + (size_t)n0 * K;

    const int a_row = t >> 3;
    const int a_kq  = (t & 7) * 4;
    const int w_row = t >> 2;
    const int w_kq  = (t & 3) * 8;

    float acc[2][8][4];
    #pragma unroll
    for (int m = 0; m < 2; m++)
        #pragma unroll
        for (int n = 0; n < 8; n++)
            #pragma unroll
            for (int e = 0; e < 4; e++) acc[m][n][e] = 0.f;

    const int nIter = K >> 5;

    float4 aR[4];
    uint4  wR[2];

    #pragma unroll
    for (int p = 0; p < 4; p++)
        aR[p] = *(const float4*)(Ab + (size_t)(a_row + p * 32) * K + a_kq);
    #pragma unroll
    for (int p = 0; p < 2; p++)
        wR[p] = *(const uint4*)(Wb + (size_t)(w_row + p * 64) * K + w_kq);

    {
        __half* sA = sm;
        __half* sW = sm + TILE_E;
        #pragma unroll
        for (int p = 0; p < 4; p++) {
            int off = (a_row + p * 32) * BKP + a_kq;
            *(uint2*)&sA[off] = make_uint2(cvt2h(aR[p].x, aR[p].y),
                                           cvt2h(aR[p].z, aR[p].w));
        }
        #pragma unroll
        for (int p = 0; p < 2; p++) {
            int off = (w_row + p * 64) * BKP + w_kq;
            *(uint4*)&sW[off] = wR[p];
        }
    }
    __syncthreads();

    // ldmatrix lane addressing (patterns proven in flash kernel)
    const uint32_t a_lrow = (l & 7) + ((l >> 3) & 1) * 8;
    const uint32_t a_lseg = (l >> 4) * 8;
    const uint32_t w_lrow = (l & 7) + (l >> 4) * 8;
    const uint32_t w_lseg = ((l >> 3) & 1) * 8;

    for (int it = 0; it < nIter; it++) {
        const int cur = it & 1;
        const bool more = (it + 1 < nIter);
        if (more) {
            const int kt = (it + 1) << 5;
            #pragma unroll
            for (int p = 0; p < 4; p++)
                aR[p] = *(const float4*)(Ab + (size_t)(a_row + p * 32) * K + kt + a_kq);
            #pragma unroll
            for (int p = 0; p < 2; p++)
                wR[p] = *(const uint4*)(Wb + (size_t)(w_row + p * 64) * K + kt + w_kq);
        }

        {
            const uint32_t bA = sbase + (cur * STAGE_E) * 2;
            const uint32_t bW = bA + TILE_E * 2;
            // HOIST: all 12 ldmatrix of this chunk before any mma.
            uint32_t ah[2][2][4];      // [ks][mb]
            uint32_t wh[2][4][4];      // [ks][g]
            #pragma unroll
            for (int ks = 0; ks < 2; ks++) {
                const int k0 = ks * 16;
                #pragma unroll
                for (int mb = 0; mb < 2; mb++) {
                    uint32_t row = wm * 32 + mb * 16 + a_lrow;
                    ldmx4(ah[ks][mb], bA + (row * BKP + k0 + a_lseg) * 2);
                }
                #pragma unroll
                for (int g = 0; g < 4; g++) {
                    uint32_t row = wn * 64 + g * 16 + w_lrow;
                    ldmx4(wh[ks][g], bW + (row * BKP + k0 + w_lseg) * 2);
                }
            }
            // Pure mma stream.
            #pragma unroll
            for (int ks = 0; ks < 2; ks++) {
                #pragma unroll
                for (int g = 0; g < 4; g++) {
                    uint32_t b0[2] = {wh[ks][g][0], wh[ks][g][1]};
                    uint32_t b1[2] = {wh[ks][g][2], wh[ks][g][3]};
                    #pragma unroll
                    for (int mb = 0; mb < 2; mb++) {
                        mma16816(acc[mb][2 * g],     ah[ks][mb], b0);
                        mma16816(acc[mb][2 * g + 1], ah[ks][mb], b1);
                    }
                }
            }
        }

        if (more) {
            __half* sA = sm + (cur ^ 1) * STAGE_E;
            __half* sW = sA + TILE_E;
            #pragma unroll
            for (int p = 0; p < 4; p++) {
                int off = (a_row + p * 32) * BKP + a_kq;
                *(uint2*)&sA[off] = make_uint2(cvt2h(aR[p].x, aR[p].y),
                                               cvt2h(aR[p].z, aR[p].w));
            }
            #pragma unroll
            for (int p = 0; p < 2; p++) {
                int off = (w_row + p * 64) * BKP + w_kq;
                *(uint4*)&sW[off] = wR[p];
            }
        }
        __syncthreads();
    }

    float* dst; int nbase; size_t Nout;
    if (mode == 2) {
        int which = n0 / 768;
        dst = (which == 0) ? C0 : ((which == 1) ? C1 : C2);
        nbase = n0 % 768;
        Nout = 768;
    } else {
        dst = C0; nbase = n0; Nout = (size_t)N;
    }
    const int rbase = m0 + wm * 32 + (l >> 2);
    #pragma unroll
    for (int m = 0; m < 2; m++) {
        #pragma unroll
        for (int n = 0; n < 8; n++) {
            int colA = n0 + wn * 64 + n * 8 + (l & 3) * 2;
            int colC = nbase + wn * 64 + n * 8 + (l & 3) * 2;
            float b0 = bias ? bias[colA]     : 0.f;
            float b1 = bias ? bias[colA + 1] : 0.f;
            float v0 = acc[m][n][0] + b0;
            float v1 = acc[m][n][1] + b1;
            float v2 = acc[m][n][2] + b0;
            float v3 = acc[m][n][3] + b1;
            if (mode == 1) {
                v0 = gelu_exact(v0); v1 = gelu_exact(v1);
                v2 = gelu_exact(v2); v3 = gelu_exact(v3);
            }
            size_t r0 = (size_t)(rbase + m * 16) * Nout + colC;
            size_t r1 = (size_t)(rbase + m * 16 + 8) * Nout + colC;
            *(float2*)&dst[r0] = make_float2(v0, v1);
            *(float2*)&dst[r1] = make_float2(v2, v3);
        }
    }
}

// ---------------------------------------------------------------------------
// Flash attention on mma.sync (causal), pure fp16 operands, fp32 accum.
// Q (scaled 1/8), K, V, P all single fp16.  (R12 version, unchanged.)
// ---------------------------------------------------------------------------
#define FLD 72
#define FATT_SMEM (3 * 64 * FLD * 2)   // 27648 bytes

__global__ void __launch_bounds__(128, 3) flash_mma_kernel(
    const float* __restrict__ Q, const float* __restrict__ K,
    const float* __restrict__ V, float* __restrict__ O)
{
    extern __shared__ __half sa[];
    const uint32_t sb  = smem_u32(sa);
    const uint32_t bQh = sb;
    const uint32_t bKh = sb + 1 * 9216;
    const uint32_t bVh = sb + 2 * 9216;
    __half* sQh = sa;
    __half* sKh = sa + 64 * FLD;
    __half* sVh = sa + 2 * 64 * FLD;

    const int qt = blockIdx.x;
    const int bh = blockIdx.y;
    const int b  = bh / Hh;
    const int h  = bh % Hh;
    const int t  = threadIdx.x;
    const int w  = t >> 5, ln = t & 31;
    const int wrow = w * 16;
    const size_t base = (size_t)b * Ss * Dd + (size_t)h * DHh;

    {
        const int row = t >> 1, co = (t & 1) * 32;
        const float* src = Q + base + (size_t)(qt * 64 + row) * Dd + co;
        #pragma unroll
        for (int i = 0; i < 8; i++) {
            float4 v = *(const float4*)(src + i * 4);
            *(uint2*)&sQh[row * FLD + co + i * 4] =
                make_uint2(cvt2h(v.x * 0.125f, v.y * 0.125f),
                           cvt2h(v.z * 0.125f, v.w * 0.125f));
        }
    }
    __syncthreads();

    uint32_t qh[4][4];
    {
        const uint32_t qrow = wrow + (ln & 7) + ((ln >> 3) & 1) * 8;
        const uint32_t cofs = ((ln >> 4)) * 8;
        #pragma unroll
        for (int k = 0; k < 4; k++) {
            uint32_t off = (qrow * FLD + k * 16 + cofs) * 2;
            ldmx4(qh[k], bQh + off);
        }
    }

    float oacc[8][4];
    #pragma unroll
    for (int f = 0; f < 8; f++)
        #pragma unroll
        for (int e = 0; e < 4; e++) oacc[f][e] = 0.f;
    float rm0 = -1e30f, rm1 = -1e30f, den0 = 0.f, den1 = 0.f;

    const int lr0 = wrow + (ln >> 2);
    const int lr1 = lr0 + 8;

    for (int jt = 0; jt <= qt; jt++) {
        __syncthreads();
        {
            const int row = t >> 1, co = (t & 1) * 32;
            const float* ksrc = K + base + (size_t)(jt * 64 + row) * Dd + co;
            const float* vsrc = V + base + (size_t)(jt * 64 + row) * Dd + co;
            #pragma unroll
            for (int i = 0; i < 8; i++) {
                float4 kv = *(const float4*)(ksrc + i * 4);
                *(uint2*)&sKh[row * FLD + co + i * 4] =
                    make_uint2(cvt2h(kv.x, kv.y), cvt2h(kv.z, kv.w));
                float4 vv = *(const float4*)(vsrc + i * 4);
                *(uint2*)&sVh[row * FLD + co + i * 4] =
                    make_uint2(cvt2h(vv.x, vv.y), cvt2h(vv.z, vv.w));
            }
        }
        __syncthreads();

        float sacc[8][4];
        #pragma unroll
        for (int f = 0; f < 8; f++)
            #pragma unroll
            for (int e = 0; e < 4; e++) sacc[f][e] = 0.f;

        {
            const uint32_t krow_b = (ln & 7) + (ln >> 4) * 8;
            const uint32_t kcol_b = ((ln >> 3) & 1) * 8;
            #pragma unroll
            for (int k = 0; k < 4; k++) {
                #pragma unroll
                for (int j = 0; j < 4; j++) {
                    uint32_t off = ((j * 16 + krow_b) * FLD + k * 16 + kcol_b) * 2;
                    uint32_t kh[4];
                    ldmx4(kh, bKh + off);
                    uint32_t bh0[2] = {kh[0], kh[1]}, bh1[2] = {kh[2], kh[3]};
                    mma16816(sacc[2*j],   qh[k], bh0);
                    mma16816(sacc[2*j+1], qh[k], bh1);
                }
            }
        }

        if (jt == qt) {
            #pragma unroll
            for (int f = 0; f < 8; f++) {
                #pragma unroll
                for (int e = 0; e < 2; e++) {
                    int lc = 8 * f + 2 * (ln & 3) + e;
                    if (lc > lr0) sacc[f][e]     = -1e9f;
                    if (lc > lr1) sacc[f][2 + e] = -1e9f;
                }
            }
        }

        float mx0 = -1e30f, mx1 = -1e30f;
        #pragma unroll
        for (int f = 0; f < 8; f++) {
            mx0 = fmaxf(mx0, fmaxf(sacc[f][0], sacc[f][1]));
            mx1 = fmaxf(mx1, fmaxf(sacc[f][2], sacc[f][3]));
        }
        mx0 = fmaxf(mx0, __shfl_xor_sync(0xffffffffu, mx0, 1));
        mx0 = fmaxf(mx0, __shfl_xor_sync(0xffffffffu, mx0, 2));
        mx1 = fmaxf(mx1, __shfl_xor_sync(0xffffffffu, mx1, 1));
        mx1 = fmaxf(mx1, __shfl_xor_sync(0xffffffffu, mx1, 2));

        const float mn0 = fmaxf(rm0, mx0), mn1 = fmaxf(rm1, mx1);
        const float sc0 = __expf(rm0 - mn0), sc1 = __expf(rm1 - mn1);
        float ls0 = 0.f, ls1 = 0.f;
        #pragma unroll
        for (int f = 0; f < 8; f++) {
            sacc[f][0] = __expf(sacc[f][0] - mn0);
            sacc[f][1] = __expf(sacc[f][1] - mn0);
            sacc[f][2] = __expf(sacc[f][2] - mn1);
            sacc[f][3] = __expf(sacc[f][3] - mn1);
            ls0 += sacc[f][0] + sacc[f][1];
            ls1 += sacc[f][2] + sacc[f][3];
        }
        ls0 += __shfl_xor_sync(0xffffffffu, ls0, 1);
        ls0 += __shfl_xor_sync(0xffffffffu, ls0, 2);
        ls1 += __shfl_xor_sync(0xffffffffu, ls1, 1);
        ls1 += __shfl_xor_sync(0xffffffffu, ls1, 2);
        den0 = den0 * sc0 + ls0;  rm0 = mn0;
        den1 = den1 * sc1 + ls1;  rm1 = mn1;
        #pragma unroll
        for (int f = 0; f < 8; f++) {
            oacc[f][0] *= sc0; oacc[f][1] *= sc0;
            oacc[f][2] *= sc1; oacc[f][3] *= sc1;
        }

        {
            const uint32_t vrow_b = (ln & 7) + ((ln >> 3) & 1) * 8;
            const uint32_t vcol_b = (ln >> 4) * 8;
            #pragma unroll
            for (int kb = 0; kb < 4; kb++) {
                uint32_t ph[4];
                ph[0] = cvt2h(sacc[2*kb][0],   sacc[2*kb][1]);
                ph[1] = cvt2h(sacc[2*kb][2],   sacc[2*kb][3]);
                ph[2] = cvt2h(sacc[2*kb+1][0], sacc[2*kb+1][1]);
                ph[3] = cvt2h(sacc[2*kb+1][2], sacc[2*kb+1][3]);
                #pragma unroll
                for (int n16 = 0; n16 < 4; n16++) {
                    uint32_t off = ((kb * 16 + vrow_b) * FLD + n16 * 16 + vcol_b) * 2;
                    uint32_t vh[4];
                    ldmx4t(vh, bVh + off);
                    uint32_t bh0[2] = {vh[0], vh[1]}, bh1[2] = {vh[2], vh[3]};
                    mma16816(oacc[2*n16],   ph, bh0);
                    mma16816(oacc[2*n16+1], ph, bh1);
                }
            }
        }
    }

    const float inv0 = 1.f / den0, inv1 = 1.f / den1;
    float* o0 = O + base + (size_t)(qt * 64 + lr0) * Dd;
    float* o1 = O + base + (size_t)(qt * 64 + lr1) * Dd;
    #pragma unroll
    for (int f = 0; f < 8; f++) {
        int c = 8 * f + 2 * (ln & 3);
        *(float2*)&o0[c] = make_float2(oacc[f][0] * inv0, oacc[f][1] * inv0);
        *(float2*)&o1[c] = make_float2(oacc[f][2] * inv1, oacc[f][3] * inv1);
    }
}

// ----------------------------------------------------------------------------
// Fused residual + LayerNorm
// ----------------------------------------------------------------------------
__global__ void __launch_bounds__(256) ln_kernel(
    const float* __restrict__ A, const float* __restrict__ Badd,
    const float* __restrict__ gw, const float* __restrict__ bw,
    float* __restrict__ out)
{
    __shared__ float red[64];
    __shared__ float smu, sinv;
    const size_t row = blockIdx.x;
    const int t = threadIdx.x;
    const size_t off = row * Dd;

    float v0 = A[off + t]       + Badd[off + t];
    float v1 = A[off + 256 + t] + Badd[off + 256 + t];
    float v2 = A[off + 512 + t] + Badd[off + 512 + t];

    float s  = v0 + v1 + v2;
    float s2 = v0 * v0 + v1 * v1 + v2 * v2;
    #pragma unroll
    for (int o = 16; o; o >>= 1) {
        s  += __shfl_xor_sync(0xffffffffu, s, o);
        s2 += __shfl_xor_sync(0xffffffffu, s2, o);
    }
    const int w = t >> 5;
    if ((t & 31) == 0) { red[w] = s; red[w + 32] = s2; }
    __syncthreads();
    if (t == 0) {
        float S = 0.f, S2 = 0.f;
        #pragma unroll
        for (int i = 0; i < 8; i++) { S += red[i]; S2 += red[i + 32]; }
        float mu  = S * (1.f / 768.f);
        float var = S2 * (1.f / 768.f) - mu * mu;
        smu  = mu;
        sinv = rsqrtf(var + 1e-5f);
    }
    __syncthreads();
    const float mu = smu, inv = sinv;
    out[off + t]       = (v0 - mu) * inv * gw[t]       + bw[t];
    out[off + 256 + t] = (v1 - mu) * inv * gw[t + 256] + bw[t + 256];
    out[off + 512 + t] = (v2 - mu) * inv * gw[t + 512] + bw[t + 512];
}

// ----------------------------------------------------------------------------
// Host launcher
// ----------------------------------------------------------------------------
extern "C" void kernel_launch(void* const* d_in, const int* in_sizes, int n_in,
                              void* d_out, int out_size)
{
    (void)in_sizes; (void)n_in; (void)out_size;

    const float* x     = (const float*)d_in[0];
    const float* Wq    = (const float*)d_in[2];
    const float* Wk    = (const float*)d_in[3];
    const float* Wv    = (const float*)d_in[4];
    const float* Wo    = (const float*)d_in[5];
    const float* bo    = (const float*)d_in[6];
    const float* ln1_g = (const float*)d_in[7];
    const float* ln1_b = (const float*)d_in[8];
    const float* W1    = (const float*)d_in[9];
    const float* b1    = (const float*)d_in[10];
    const float* W2    = (const float*)d_in[11];
    const float* b2    = (const float*)d_in[12];
    const float* ln2_g = (const float*)d_in[13];
    const float* ln2_b = (const float*)d_in[14];

    float *px, *pq, *pk, *pv, *pattn, *pmid;
    cudaGetSymbolAddress((void**)&px,    g_x);
    cudaGetSymbolAddress((void**)&pq,    g_q);
    cudaGetSymbolAddress((void**)&pk,    g_k);
    cudaGetSymbolAddress((void**)&pv,    g_v);
    cudaGetSymbolAddress((void**)&pattn, g_attn);
    cudaGetSymbolAddress((void**)&pmid,  g_mid);

    __half *qkvw, *wow, *w1w, *w2w;
    cudaGetSymbolAddress((void**)&qkvw, g_wqkv);
    cudaGetSymbolAddress((void**)&wow,  g_wo);
    cudaGetSymbolAddress((void**)&w1w,  g_w1);
    cudaGetSymbolAddress((void**)&w2w,  g_w2);

    cudaFuncSetAttribute(flash_mma_kernel,
                         cudaFuncAttributeMaxDynamicSharedMemorySize, FATT_SMEM);
    cudaFuncSetAttribute(tc_gemm_kernel,
                         cudaFuncAttributeMaxDynamicSharedMemorySize, GEMM_SMEM);

    const size_t DD = (size_t)Dd * Dd;
    const size_t DF = (size_t)Dd * Ff;

    // Preprocess weights (3 launches)
    {
        dim3 tb(256);
        transpose_dd_kernel<<<dim3(24, 24, 16), tb>>>(
            Wq, Wk, Wv, Wo, qkvw, wow);
        transpose_split_kernel<<<dim3(Ff/32, Dd/32, Ll), tb>>>(
            W1, w1w, Dd, Ff, DF);
        transpose_split_kernel<<<dim3(Dd/32, Ff/32, Ll), tb>>>(
            W2, w2w, Ff, Dd, DF);
    }

    const dim3 blk(256);
    const dim3 fblk(128);
    const dim3 gA(Ss / 64, Bb * Hh);

    const float* cur_x = x;
    for (int l = 0; l < Ll; l++) {
        const float* bo_l = bo + (size_t)l * Dd;
        const float* g1_l = ln1_g + (size_t)l * Dd;
        const float* c1_l = ln1_b + (size_t)l * Dd;
        const float* b1_l = b1 + (size_t)l * Ff;
        const float* b2_l = b2 + (size_t)l * Dd;
        const float* g2_l = ln2_g + (size_t)l * Dd;
        const float* c2_l = ln2_b + (size_t)l * Dd;

        // Fused QKV: N=2304, epilogue routes to q/k/v
        tc_gemm_kernel<<<dim3(18, 64), blk, GEMM_SMEM>>>(
            cur_x, qkvw + l * 3 * DD, nullptr,
            pq, pk, pv, 2304, 768, 2);

        // causal flash attention (mma) -> merged av in g_attn
        flash_mma_kernel<<<gA, fblk, FATT_SMEM>>>(pq, pk, pv, pattn);

        // attn_out = av @ Wo + bo  (into pq)
        tc_gemm_kernel<<<dim3(6, 64), blk, GEMM_SMEM>>>(
            pattn, wow + l * DD, bo_l,
            pq, pq, pq, 768, 768, 0);

        // h = LN(x + attn_out)
        ln_kernel<<<Mrows, blk>>>(cur_x, pq, g1_l, c1_l, px);

        // mid = gelu(h @ W1 + b1)
        tc_gemm_kernel<<<dim3(24, 64), blk, GEMM_SMEM>>>(
            px, w1w + l * DF, b1_l,
            pmid, pmid, pmid, 3072, 768, 1);

        // f = mid @ W2 + b2  (into pattn)
        tc_gemm_kernel<<<dim3(6, 64), blk, GEMM_SMEM>>>(
            pmid, w2w + l * DF, b2_l,
            pattn, pattn, pattn, 768, 3072, 0);

        // x_next = LN(h + f); last layer writes d_out
        float* dst = (l == Ll - 1) ? (float*)d_out : px;
        ln_kernel<<<Mrows, blk>>>(px, pattn, g2_l, c2_l, dst);

        cur_x = px;
    }
}

// round 17
// speedup vs baseline: 1.0032x; 1.0032x over previous
#include <cuda_runtime.h>
#include <cuda_bf16.h>
#include <cuda_fp16.h>
#include <math.h>
#include <stdint.h>

// Problem constants
#define Bb 4
#define Ss 2048
#define Dd 768
#define Hh 12
#define Ff 3072
#define Ll 4
#define DHh 64
#define Mrows (Bb*Ss)   // 8192

// ---------------------------------------------------------------------------
// Scratch (device globals; allocation is forbidden)
// ---------------------------------------------------------------------------
__device__ float g_x[Bb*Ss*Dd];
__device__ float g_q[Bb*Ss*Dd];
__device__ float g_k[Bb*Ss*Dd];
__device__ float g_v[Bb*Ss*Dd];
__device__ float g_attn[Bb*Ss*Dd];
__device__ float g_mid[Bb*Ss*Ff];

// Preprocessed (transposed [N,K] K-major) fp16 weights
__device__ __half g_wqkv[Ll*3*Dd*Dd];
__device__ __half g_wo[Ll*Dd*Dd];
__device__ __half g_w1[Ll*Ff*Dd];
__device__ __half g_w2[Ll*Dd*Ff];

__device__ __forceinline__ float gelu_exact(float v) {
    return 0.5f * v * (1.0f + erff(v * 0.70710678118654752f));
}

// fp16 mma: D = A(f16) * B(f16) + D, fp32 accum
__device__ __forceinline__ void mma16816(float* c, const uint32_t* a,
                                         const uint32_t* b) {
    asm volatile(
        "mma.sync.aligned.m16n8k16.row.col.f32.f16.f16.f32 "
        "{%0,%1,%2,%3}, {%4,%5,%6,%7}, {%8,%9}, {%0,%1,%2,%3};"
        : "+f"(c[0]), "+f"(c[1]), "+f"(c[2]), "+f"(c[3])
        : "r"(a[0]), "r"(a[1]), "r"(a[2]), "r"(a[3]), "r"(b[0]), "r"(b[1]));
}

__device__ __forceinline__ void ldmx4(uint32_t* r, uint32_t addr) {
    asm volatile(
        "ldmatrix.sync.aligned.m8n8.x4.shared.b16 {%0,%1,%2,%3}, [%4];"
        : "=r"(r[0]), "=r"(r[1]), "=r"(r[2]), "=r"(r[3]) : "r"(addr));
}

__device__ __forceinline__ void ldmx4t(uint32_t* r, uint32_t addr) {
    asm volatile(
        "ldmatrix.sync.aligned.m8n8.x4.trans.shared.b16 {%0,%1,%2,%3}, [%4];"
        : "=r"(r[0]), "=r"(r[1]), "=r"(r[2]), "=r"(r[3]) : "r"(addr));
}

__device__ __forceinline__ uint32_t smem_u32(const void* p) {
    uint32_t a;
    asm("{ .reg .u64 tmp; cvta.to.shared.u64 tmp, %1; cvt.u32.u64 %0, tmp; }"
        : "=r"(a) : "l"(p));
    return a;
}

__device__ __forceinline__ uint32_t pack_h2(__half a, __half b) {
    __half2 p; p.x = a; p.y = b;
    return *(uint32_t*)&p;
}

__device__ __forceinline__ uint32_t cvt2h(float x, float y) {
    return pack_h2(__float2half_rn(x), __float2half_rn(y));
}

// ---------------------------------------------------------------------------
// Weight preprocessing (3 launches): transpose [K,N] -> [N,K], fp16.
// ---------------------------------------------------------------------------
__global__ void __launch_bounds__(256) transpose_dd_kernel(
    const float* __restrict__ Wq, const float* __restrict__ Wk,
    const float* __restrict__ Wv, const float* __restrict__ Wo,
    __half* __restrict__ qkv, __half* __restrict__ wo)
{
    __shared__ float tile[32][33];
    const int z = blockIdx.z;
    const int layer = z >> 2, which = z & 3;
    const size_t DD = (size_t)Dd * Dd;
    const float* src =
        (which == 0 ? Wq : which == 1 ? Wk : which == 2 ? Wv : Wo)
        + (size_t)layer * DD;
    __half* oh;
    int rowOff;
    if (which < 3) {
        oh = qkv + (size_t)layer * 3 * DD;
        rowOff = which * Dd;
    } else {
        oh = wo + (size_t)layer * DD;
        rowOff = 0;
    }
    const int nb = blockIdx.x * 32, kb = blockIdx.y * 32;
    const int tx = threadIdx.x & 31, ty = threadIdx.x >> 5;
    #pragma unroll
    for (int j = 0; j < 32; j += 8)
        tile[ty + j][tx] = src[(size_t)(kb + ty + j) * Dd + nb + tx];
    __syncthreads();
    #pragma unroll
    for (int j = 0; j < 32; j += 8) {
        float v = tile[tx][ty + j];
        int n = nb + ty + j, k = kb + tx;
        oh[(size_t)(rowOff + n) * Dd + k] = __float2half_rn(v);
    }
}

__global__ void __launch_bounds__(256) transpose_split_kernel(
    const float* __restrict__ W, __half* __restrict__ oh,
    int K, int N, size_t LS)
{
    __shared__ float tile[32][33];
    const float* Wl = W + (size_t)blockIdx.z * LS;
    __half* ohl = oh + (size_t)blockIdx.z * LS;
    const int nb = blockIdx.x * 32, kb = blockIdx.y * 32;
    const int tx = threadIdx.x & 31, ty = threadIdx.x >> 5;
    #pragma unroll
    for (int j = 0; j < 32; j += 8)
        tile[ty + j][tx] = Wl[(size_t)(kb + ty + j) * N + nb + tx];
    __syncthreads();
    #pragma unroll
    for (int j = 0; j < 32; j += 8) {
        float v = tile[tx][ty + j];
        int n = nb + ty + j, k = kb + tx;
        ohl[(size_t)n * K + k] = __float2half_rn(v);
    }
}

// ---------------------------------------------------------------------------
// Tensor-core GEMM (R15 + hoisted LDSM): CTA 128x128, 8 warps (32x64 warp
// tile), BK=32, double-buffered smem, register-prefetch LDG, one sync per
// chunk. ALL 12 ldmatrix of the chunk issue before any mma so their
// latencies overlap; the 32 mma then stream without per-group LDS stalls.
// PURE fp16: C = A(f16) * W(f16)^T, fp32 accum.
// mode: 0 = +bias, 1 = +bias +exact GELU, 2 = QKV split (768-col outputs).
// ---------------------------------------------------------------------------
#define BKP 40
#define TILE_E (128 * BKP)
#define STAGE_E (2 * TILE_E)          // A, W
#define GEMM_SMEM (2 * STAGE_E * 2)   // 40960 B

__global__ void __launch_bounds__(256, 1)
tc_gemm_kernel(const float* __restrict__ A,
               const __half* __restrict__ W,
               const float* __restrict__ bias,
               float* __restrict__ C0, float* __restrict__ C1,
               float* __restrict__ C2,
               int N, int K, int mode)
{
    extern __shared__ __half sm[];
    const uint32_t sbase = smem_u32(sm);
    const int t   = threadIdx.x;
    const int wid = t >> 5, l = t & 31;
    const int wm  = wid & 3;
    const int wn  = wid >> 2;
    const int n0  = blockIdx.x * 128;
    const int m0  = blockIdx.y * 128;

    const float* Ab = A + (size_t)m0 * K;
    const __half* Wb = W + (size_t)n0 * K;

    const int a_row = t >> 3;
    const int a_kq  = (t & 7) * 4;
    const int w_row = t >> 2;
    const int w_kq  = (t & 3) * 8;

    float acc[2][8][4];
    #pragma unroll
    for (int m = 0; m < 2; m++)
        #pragma unroll
        for (int n = 0; n < 8; n++)
            #pragma unroll
            for (int e = 0; e < 4; e++) acc[m][n][e] = 0.f;

    const int nIter = K >> 5;

    float4 aR[4];
    uint4  wR[2];

    #pragma unroll
    for (int p = 0; p < 4; p++)
        aR[p] = *(const float4*)(Ab + (size_t)(a_row + p * 32) * K + a_kq);
    #pragma unroll
    for (int p = 0; p < 2; p++)
        wR[p] = *(const uint4*)(Wb + (size_t)(w_row + p * 64) * K + w_kq);

    {
        __half* sA = sm;
        __half* sW = sm + TILE_E;
        #pragma unroll
        for (int p = 0; p < 4; p++) {
            int off = (a_row + p * 32) * BKP + a_kq;
            *(uint2*)&sA[off] = make_uint2(cvt2h(aR[p].x, aR[p].y),
                                           cvt2h(aR[p].z, aR[p].w));
        }
        #pragma unroll
        for (int p = 0; p < 2; p++) {
            int off = (w_row + p * 64) * BKP + w_kq;
            *(uint4*)&sW[off] = wR[p];
        }
    }
    __syncthreads();

    // ldmatrix lane addressing (patterns proven in flash kernel)
    const uint32_t a_lrow = (l & 7) + ((l >> 3) & 1) * 8;
    const uint32_t a_lseg = (l >> 4) * 8;
    const uint32_t w_lrow = (l & 7) + (l >> 4) * 8;
    const uint32_t w_lseg = ((l >> 3) & 1) * 8;

    for (int it = 0; it < nIter; it++) {
        const int cur = it & 1;
        const bool more = (it + 1 < nIter);
        if (more) {
            const int kt = (it + 1) << 5;
            #pragma unroll
            for (int p = 0; p < 4; p++)
                aR[p] = *(const float4*)(Ab + (size_t)(a_row + p * 32) * K + kt + a_kq);
            #pragma unroll
            for (int p = 0; p < 2; p++)
                wR[p] = *(const uint4*)(Wb + (size_t)(w_row + p * 64) * K + kt + w_kq);
        }

        {
            const uint32_t bA = sbase + (cur * STAGE_E) * 2;
            const uint32_t bW = bA + TILE_E * 2;
            // HOIST: all 12 ldmatrix of this chunk before any mma.
            uint32_t ah[2][2][4];      // [ks][mb]
            uint32_t wh[2][4][4];      // [ks][g]
            #pragma unroll
            for (int ks = 0; ks < 2; ks++) {
                const int k0 = ks * 16;
                #pragma unroll
                for (int mb = 0; mb < 2; mb++) {
                    uint32_t row = wm * 32 + mb * 16 + a_lrow;
                    ldmx4(ah[ks][mb], bA + (row * BKP + k0 + a_lseg) * 2);
                }
                #pragma unroll
                for (int g = 0; g < 4; g++) {
                    uint32_t row = wn * 64 + g * 16 + w_lrow;
                    ldmx4(wh[ks][g], bW + (row * BKP + k0 + w_lseg) * 2);
                }
            }
            // Pure mma stream.
            #pragma unroll
            for (int ks = 0; ks < 2; ks++) {
                #pragma unroll
                for (int g = 0; g < 4; g++) {
                    uint32_t b0[2] = {wh[ks][g][0], wh[ks][g][1]};
                    uint32_t b1[2] = {wh[ks][g][2], wh[ks][g][3]};
                    #pragma unroll
                    for (int mb = 0; mb < 2; mb++) {
                        mma16816(acc[mb][2 * g],     ah[ks][mb], b0);
                        mma16816(acc[mb][2 * g + 1], ah[ks][mb], b1);
                    }
                }
            }
        }

        if (more) {
            __half* sA = sm + (cur ^ 1) * STAGE_E;
            __half* sW = sA + TILE_E;
            #pragma unroll
            for (int p = 0; p < 4; p++) {
                int off = (a_row + p * 32) * BKP + a_kq;
                *(uint2*)&sA[off] = make_uint2(cvt2h(aR[p].x, aR[p].y),
                                               cvt2h(aR[p].z, aR[p].w));
            }
            #pragma unroll
            for (int p = 0; p < 2; p++) {
                int off = (w_row + p * 64) * BKP + w_kq;
                *(uint4*)&sW[off] = wR[p];
            }
        }
        __syncthreads();
    }

    float* dst; int nbase; size_t Nout;
    if (mode == 2) {
        int which = n0 / 768;
        dst = (which == 0) ? C0 : ((which == 1) ? C1 : C2);
        nbase = n0 % 768;
        Nout = 768;
    } else {
        dst = C0; nbase = n0; Nout = (size_t)N;
    }
    const int rbase = m0 + wm * 32 + (l >> 2);
    #pragma unroll
    for (int m = 0; m < 2; m++) {
        #pragma unroll
        for (int n = 0; n < 8; n++) {
            int colA = n0 + wn * 64 + n * 8 + (l & 3) * 2;
            int colC = nbase + wn * 64 + n * 8 + (l & 3) * 2;
            float b0 = bias ? bias[colA]     : 0.f;
            float b1 = bias ? bias[colA + 1] : 0.f;
            float v0 = acc[m][n][0] + b0;
            float v1 = acc[m][n][1] + b1;
            float v2 = acc[m][n][2] + b0;
            float v3 = acc[m][n][3] + b1;
            if (mode == 1) {
                v0 = gelu_exact(v0); v1 = gelu_exact(v1);
                v2 = gelu_exact(v2); v3 = gelu_exact(v3);
            }
            size_t r0 = (size_t)(rbase + m * 16) * Nout + colC;
            size_t r1 = (size_t)(rbase + m * 16 + 8) * Nout + colC;
            *(float2*)&dst[r0] = make_float2(v0, v1);
            *(float2*)&dst[r1] = make_float2(v2, v3);
        }
    }
}

// ---------------------------------------------------------------------------
// Flash attention on mma.sync (causal), pure fp16 operands, fp32 accum.
// Q (scaled 1/8), K, V, P all single fp16.  (R12 version, unchanged.)
// ---------------------------------------------------------------------------
#define FLD 72
#define FATT_SMEM (3 * 64 * FLD * 2)   // 27648 bytes

__global__ void __launch_bounds__(128, 3) flash_mma_kernel(
    const float* __restrict__ Q, const float* __restrict__ K,
    const float* __restrict__ V, float* __restrict__ O)
{
    extern __shared__ __half sa[];
    const uint32_t sb  = smem_u32(sa);
    const uint32_t bQh = sb;
    const uint32_t bKh = sb + 1 * 9216;
    const uint32_t bVh = sb + 2 * 9216;
    __half* sQh = sa;
    __half* sKh = sa + 64 * FLD;
    __half* sVh = sa + 2 * 64 * FLD;

    const int qt = blockIdx.x;
    const int bh = blockIdx.y;
    const int b  = bh / Hh;
    const int h  = bh % Hh;
    const int t  = threadIdx.x;
    const int w  = t >> 5, ln = t & 31;
    const int wrow = w * 16;
    const size_t base = (size_t)b * Ss * Dd + (size_t)h * DHh;

    {
        const int row = t >> 1, co = (t & 1) * 32;
        const float* src = Q + base + (size_t)(qt * 64 + row) * Dd + co;
        #pragma unroll
        for (int i = 0; i < 8; i++) {
            float4 v = *(const float4*)(src + i * 4);
            *(uint2*)&sQh[row * FLD + co + i * 4] =
                make_uint2(cvt2h(v.x * 0.125f, v.y * 0.125f),
                           cvt2h(v.z * 0.125f, v.w * 0.125f));
        }
    }
    __syncthreads();

    uint32_t qh[4][4];
    {
        const uint32_t qrow = wrow + (ln & 7) + ((ln >> 3) & 1) * 8;
        const uint32_t cofs = ((ln >> 4)) * 8;
        #pragma unroll
        for (int k = 0; k < 4; k++) {
            uint32_t off = (qrow * FLD + k * 16 + cofs) * 2;
            ldmx4(qh[k], bQh + off);
        }
    }

    float oacc[8][4];
    #pragma unroll
    for (int f = 0; f < 8; f++)
        #pragma unroll
        for (int e = 0; e < 4; e++) oacc[f][e] = 0.f;
    float rm0 = -1e30f, rm1 = -1e30f, den0 = 0.f, den1 = 0.f;

    const int lr0 = wrow + (ln >> 2);
    const int lr1 = lr0 + 8;

    for (int jt = 0; jt <= qt; jt++) {
        __syncthreads();
        {
            const int row = t >> 1, co = (t & 1) * 32;
            const float* ksrc = K + base + (size_t)(jt * 64 + row) * Dd + co;
            const float* vsrc = V + base + (size_t)(jt * 64 + row) * Dd + co;
            #pragma unroll
            for (int i = 0; i < 8; i++) {
                float4 kv = *(const float4*)(ksrc + i * 4);
                *(uint2*)&sKh[row * FLD + co + i * 4] =
                    make_uint2(cvt2h(kv.x, kv.y), cvt2h(kv.z, kv.w));
                float4 vv = *(const float4*)(vsrc + i * 4);
                *(uint2*)&sVh[row * FLD + co + i * 4] =
                    make_uint2(cvt2h(vv.x, vv.y), cvt2h(vv.z, vv.w));
            }
        }
        __syncthreads();

        float sacc[8][4];
        #pragma unroll
        for (int f = 0; f < 8; f++)
            #pragma unroll
            for (int e = 0; e < 4; e++) sacc[f][e] = 0.f;

        {
            const uint32_t krow_b = (ln & 7) + (ln >> 4) * 8;
            const uint32_t kcol_b = ((ln >> 3) & 1) * 8;
            #pragma unroll
            for (int k = 0; k < 4; k++) {
                #pragma unroll
                for (int j = 0; j < 4; j++) {
                    uint32_t off = ((j * 16 + krow_b) * FLD + k * 16 + kcol_b) * 2;
                    uint32_t kh[4];
                    ldmx4(kh, bKh + off);
                    uint32_t bh0[2] = {kh[0], kh[1]}, bh1[2] = {kh[2], kh[3]};
                    mma16816(sacc[2*j],   qh[k], bh0);
                    mma16816(sacc[2*j+1], qh[k], bh1);
                }
            }
        }

        if (jt == qt) {
            #pragma unroll
            for (int f = 0; f < 8; f++) {
                #pragma unroll
                for (int e = 0; e < 2; e++) {
                    int lc = 8 * f + 2 * (ln & 3) + e;
                    if (lc > lr0) sacc[f][e]     = -1e9f;
                    if (lc > lr1) sacc[f][2 + e] = -1e9f;
                }
            }
        }

        float mx0 = -1e30f, mx1 = -1e30f;
        #pragma unroll
        for (int f = 0; f < 8; f++) {
            mx0 = fmaxf(mx0, fmaxf(sacc[f][0], sacc[f][1]));
            mx1 = fmaxf(mx1, fmaxf(sacc[f][2], sacc[f][3]));
        }
        mx0 = fmaxf(mx0, __shfl_xor_sync(0xffffffffu, mx0, 1));
        mx0 = fmaxf(mx0, __shfl_xor_sync(0xffffffffu, mx0, 2));
        mx1 = fmaxf(mx1, __shfl_xor_sync(0xffffffffu, mx1, 1));
        mx1 = fmaxf(mx1, __shfl_xor_sync(0xffffffffu, mx1, 2));

        const float mn0 = fmaxf(rm0, mx0), mn1 = fmaxf(rm1, mx1);
        const float sc0 = __expf(rm0 - mn0), sc1 = __expf(rm1 - mn1);
        float ls0 = 0.f, ls1 = 0.f;
        #pragma unroll
        for (int f = 0; f < 8; f++) {
            sacc[f][0] = __expf(sacc[f][0] - mn0);
            sacc[f][1] = __expf(sacc[f][1] - mn0);
            sacc[f][2] = __expf(sacc[f][2] - mn1);
            sacc[f][3] = __expf(sacc[f][3] - mn1);
            ls0 += sacc[f][0] + sacc[f][1];
            ls1 += sacc[f][2] + sacc[f][3];
        }
        ls0 += __shfl_xor_sync(0xffffffffu, ls0, 1);
        ls0 += __shfl_xor_sync(0xffffffffu, ls0, 2);
        ls1 += __shfl_xor_sync(0xffffffffu, ls1, 1);
        ls1 += __shfl_xor_sync(0xffffffffu, ls1, 2);
        den0 = den0 * sc0 + ls0;  rm0 = mn0;
        den1 = den1 * sc1 + ls1;  rm1 = mn1;
        #pragma unroll
        for (int f = 0; f < 8; f++) {
            oacc[f][0] *= sc0; oacc[f][1] *= sc0;
            oacc[f][2] *= sc1; oacc[f][3] *= sc1;
        }

        {
            const uint32_t vrow_b = (ln & 7) + ((ln >> 3) & 1) * 8;
            const uint32_t vcol_b = (ln >> 4) * 8;
            #pragma unroll
            for (int kb = 0; kb < 4; kb++) {
                uint32_t ph[4];
                ph[0] = cvt2h(sacc[2*kb][0],   sacc[2*kb][1]);
                ph[1] = cvt2h(sacc[2*kb][2],   sacc[2*kb][3]);
                ph[2] = cvt2h(sacc[2*kb+1][0], sacc[2*kb+1][1]);
                ph[3] = cvt2h(sacc[2*kb+1][2], sacc[2*kb+1][3]);
                #pragma unroll
                for (int n16 = 0; n16 < 4; n16++) {
                    uint32_t off = ((kb * 16 + vrow_b) * FLD + n16 * 16 + vcol_b) * 2;
                    uint32_t vh[4];
                    ldmx4t(vh, bVh + off);
                    uint32_t bh0[2] = {vh[0], vh[1]}, bh1[2] = {vh[2], vh[3]};
                    mma16816(oacc[2*n16],   ph, bh0);
                    mma16816(oacc[2*n16+1], ph, bh1);
                }
            }
        }
    }

    const float inv0 = 1.f / den0, inv1 = 1.f / den1;
    float* o0 = O + base + (size_t)(qt * 64 + lr0) * Dd;
    float* o1 = O + base + (size_t)(qt * 64 + lr1) * Dd;
    #pragma unroll
    for (int f = 0; f < 8; f++) {
        int c = 8 * f + 2 * (ln & 3);
        *(float2*)&o0[c] = make_float2(oacc[f][0] * inv0, oacc[f][1] * inv0);
        *(float2*)&o1[c] = make_float2(oacc[f][2] * inv1, oacc[f][3] * inv1);
    }
}

// ----------------------------------------------------------------------------
// Fused residual + LayerNorm
// ----------------------------------------------------------------------------
__global__ void __launch_bounds__(256) ln_kernel(
    const float* __restrict__ A, const float* __restrict__ Badd,
    const float* __restrict__ gw, const float* __restrict__ bw,
    float* __restrict__ out)
{
    __shared__ float red[64];
    __shared__ float smu, sinv;
    const size_t row = blockIdx.x;
    const int t = threadIdx.x;
    const size_t off = row * Dd;

    float v0 = A[off + t]       + Badd[off + t];
    float v1 = A[off + 256 + t] + Badd[off + 256 + t];
    float v2 = A[off + 512 + t] + Badd[off + 512 + t];

    float s  = v0 + v1 + v2;
    float s2 = v0 * v0 + v1 * v1 + v2 * v2;
    #pragma unroll
    for (int o = 16; o; o >>= 1) {
        s  += __shfl_xor_sync(0xffffffffu, s, o);
        s2 += __shfl_xor_sync(0xffffffffu, s2, o);
    }
    const int w = t >> 5;
    if ((t & 31) == 0) { red[w] = s; red[w + 32] = s2; }
    __syncthreads();
    if (t == 0) {
        float S = 0.f, S2 = 0.f;
        #pragma unroll
        for (int i = 0; i < 8; i++) { S += red[i]; S2 += red[i + 32]; }
        float mu  = S * (1.f / 768.f);
        float var = S2 * (1.f / 768.f) - mu * mu;
        smu  = mu;
        sinv = rsqrtf(var + 1e-5f);
    }
    __syncthreads();
    const float mu = smu, inv = sinv;
    out[off + t]       = (v0 - mu) * inv * gw[t]       + bw[t];
    out[off + 256 + t] = (v1 - mu) * inv * gw[t + 256] + bw[t + 256];
    out[off + 512 + t] = (v2 - mu) * inv * gw[t + 512] + bw[t + 512];
}

// ----------------------------------------------------------------------------
// Host launcher
// ----------------------------------------------------------------------------
extern "C" void kernel_launch(void* const* d_in, const int* in_sizes, int n_in,
                              void* d_out, int out_size)
{
    (void)in_sizes; (void)n_in; (void)out_size;

    const float* x     = (const float*)d_in[0];
    const float* Wq    = (const float*)d_in[2];
    const float* Wk    = (const float*)d_in[3];
    const float* Wv    = (const float*)d_in[4];
    const float* Wo    = (const float*)d_in[5];
    const float* bo    = (const float*)d_in[6];
    const float* ln1_g = (const float*)d_in[7];
    const float* ln1_b = (const float*)d_in[8];
    const float* W1    = (const float*)d_in[9];
    const float* b1    = (const float*)d_in[10];
    const float* W2    = (const float*)d_in[11];
    const float* b2    = (const float*)d_in[12];
    const float* ln2_g = (const float*)d_in[13];
    const float* ln2_b = (const float*)d_in[14];

    float *px, *pq, *pk, *pv, *pattn, *pmid;
    cudaGetSymbolAddress((void**)&px,    g_x);
    cudaGetSymbolAddress((void**)&pq,    g_q);
    cudaGetSymbolAddress((void**)&pk,    g_k);
    cudaGetSymbolAddress((void**)&pv,    g_v);
    cudaGetSymbolAddress((void**)&pattn, g_attn);
    cudaGetSymbolAddress((void**)&pmid,  g_mid);

    __half *qkvw, *wow, *w1w, *w2w;
    cudaGetSymbolAddress((void**)&qkvw, g_wqkv);
    cudaGetSymbolAddress((void**)&wow,  g_wo);
    cudaGetSymbolAddress((void**)&w1w,  g_w1);
    cudaGetSymbolAddress((void**)&w2w,  g_w2);

    cudaFuncSetAttribute(flash_mma_kernel,
                         cudaFuncAttributeMaxDynamicSharedMemorySize, FATT_SMEM);
    cudaFuncSetAttribute(tc_gemm_kernel,
                         cudaFuncAttributeMaxDynamicSharedMemorySize, GEMM_SMEM);

    const size_t DD = (size_t)Dd * Dd;
    const size_t DF = (size_t)Dd * Ff;

    // Preprocess weights (3 launches)
    {
        dim3 tb(256);
        transpose_dd_kernel<<<dim3(24, 24, 16), tb>>>(
            Wq, Wk, Wv, Wo, qkvw, wow);
        transpose_split_kernel<<<dim3(Ff/32, Dd/32, Ll), tb>>>(
            W1, w1w, Dd, Ff, DF);
        transpose_split_kernel<<<dim3(Dd/32, Ff/32, Ll), tb>>>(
            W2, w2w, Ff, Dd, DF);
    }

    const dim3 blk(256);
    const dim3 fblk(128);
    const dim3 gA(Ss / 64, Bb * Hh);

    const float* cur_x = x;
    for (int l = 0; l < Ll; l++) {
        const float* bo_l = bo + (size_t)l * Dd;
        const float* g1_l = ln1_g + (size_t)l * Dd;
        const float* c1_l = ln1_b + (size_t)l * Dd;
        const float* b1_l = b1 + (size_t)l * Ff;
        const float* b2_l = b2 + (size_t)l * Dd;
        const float* g2_l = ln2_g + (size_t)l * Dd;
        const float* c2_l = ln2_b + (size_t)l * Dd;

        // Fused QKV: N=2304, epilogue routes to q/k/v
        tc_gemm_kernel<<<dim3(18, 64), blk, GEMM_SMEM>>>(
            cur_x, qkvw + l * 3 * DD, nullptr,
            pq, pk, pv, 2304, 768, 2);

        // causal flash attention (mma) -> merged av in g_attn
        flash_mma_kernel<<<gA, fblk, FATT_SMEM>>>(pq, pk, pv, pattn);

        // attn_out = av @ Wo + bo  (into pq)
        tc_gemm_kernel<<<dim3(6, 64), blk, GEMM_SMEM>>>(
            pattn, wow + l * DD, bo_l,
            pq, pq, pq, 768, 768, 0);

        // h = LN(x + attn_out)
        ln_kernel<<<Mrows, blk>>>(cur_x, pq, g1_l, c1_l, px);

        // mid = gelu(h @ W1 + b1)
        tc_gemm_kernel<<<dim3(24, 64), blk, GEMM_SMEM>>>(
            px, w1w + l * DF, b1_l,
            pmid, pmid, pmid, 3072, 768, 1);

        // f = mid @ W2 + b2  (into pattn)
        tc_gemm_kernel<<<dim3(6, 64), blk, GEMM_SMEM>>>(
            pmid, w2w + l * DF, b2_l,
            pattn, pattn, pattn, 768, 3072, 0);

        // x_next = LN(h + f); last layer writes d_out
        float* dst = (l == Ll - 1) ? (float*)d_out : px;
        ln_kernel<<<Mrows, blk>>>(px, pattn, g2_l, c2_l, dst);

        cur_x = px;
    }
}